// round 7
// baseline (speedup 1.0000x reference)
#include <cuda_runtime.h>
#include <cuda_fp16.h>

#define BQ 64
#define TT 256
#define HU 1024
#define HD 512
#define NG 4096
#define NBLK 128
#define UPB 8           // hidden units per block
#define NKT 192         // k16 tiles: 64 (Whh0) + 64 (Wih1) + 64 (Whh1)
#define THREADS 512

// ---------------- static device scratch (no allocation allowed) -------------
__device__ float  g_Gpre[(size_t)TT * BQ * NG];
__device__ __half g_h0[2][BQ * HU];
__device__ __half g_h1[2][BQ * HU];
__device__ uint2  g_Wf[(size_t)NBLK * 4 * NKT * 32];   // recurrent weights, frag order
__device__ __half g_embed_h[(size_t)10000 * HD];       // fp16 embed
__device__ uint2  g_W0f[(size_t)(NG / 8) * 32 * 32];   // Wih0 fp16, frag order
__device__ unsigned g_cntA, g_cntB, g_flagA, g_flagB;

// smem layout for persistent kernel
#define WSM_BYTES   (4 * NKT * 32 * 8)                 // 196608
#define ABUF_OFF    WSM_BYTES
#define STAGE_BYTES 8192                               // 64 rows x 128B, SW128 swizzle
#define NSTAGE      4
#define BSUM_OFF    (ABUF_OFF + NSTAGE * STAGE_BYTES)  // 229376
#define SMEM_TOTAL  (BSUM_OFF + 128)                   // 229504

// ---------------- helpers ----------------------------------------------------
__device__ __forceinline__ void mma16h(float* c, const unsigned* a, const unsigned* b) {
    asm volatile(
        "mma.sync.aligned.m16n8k16.row.col.f32.f16.f16.f32 "
        "{%0,%1,%2,%3}, {%4,%5,%6,%7}, {%8,%9}, {%0,%1,%2,%3};\n"
        : "+f"(c[0]), "+f"(c[1]), "+f"(c[2]), "+f"(c[3])
        : "r"(a[0]), "r"(a[1]), "r"(a[2]), "r"(a[3]), "r"(b[0]), "r"(b[1]));
}
__device__ __forceinline__ void ldmA72(unsigned* a, const __half* buf, int mrow,
                                       int kcol, int lane) {
    int row = mrow + (lane & 7) + ((lane >> 3) & 1) * 8;
    int col = kcol + (lane >> 4) * 8;
    unsigned addr = (unsigned)__cvta_generic_to_shared(buf + row * 72 + col);
    asm volatile("ldmatrix.sync.aligned.m8n8.x4.shared.b16 {%0,%1,%2,%3}, [%4];"
                 : "=r"(a[0]), "=r"(a[1]), "=r"(a[2]), "=r"(a[3]) : "r"(addr));
}
// A-frag load from SW128-swizzled pitch-64-halves tile (persistent kernel)
__device__ __forceinline__ void ldmA_sw(unsigned* a, unsigned base, int mrow,
                                        int kcol, int lane) {
    int row = mrow + (lane & 7) + ((lane >> 3) & 1) * 8;
    unsigned sl = (unsigned)(kcol >> 3) + (unsigned)(lane >> 4);
    unsigned off = (unsigned)row * 128u + ((sl << 4) ^ (((unsigned)row & 7u) << 4));
    unsigned addr = base + off;
    asm volatile("ldmatrix.sync.aligned.m8n8.x4.shared.b16 {%0,%1,%2,%3}, [%4];"
                 : "=r"(a[0]), "=r"(a[1]), "=r"(a[2]), "=r"(a[3]) : "r"(addr));
}
__device__ __forceinline__ float fsig(float x) {
    return __fdividef(1.f, 1.f + __expf(-x));
}
__device__ __forceinline__ float ftanh(float x) {
    return __fdividef(2.f, 1.f + __expf(-2.f * x)) - 1.f;
}

// ---------------- init -------------------------------------------------------
__global__ void zero_kernel() {
    int i = blockIdx.x * blockDim.x + threadIdx.x;
    int n = BQ * HU / 2;
    if (i < n) {
        ((unsigned*)g_h0[0])[i] = 0u;
        ((unsigned*)g_h1[0])[i] = 0u;
    }
    if (i == 0) { g_cntA = 0u; g_cntB = 0u; g_flagA = 0u; g_flagB = 0u; }
}

// ---------------- fp32 -> fp16 embed conversion ------------------------------
__global__ void __launch_bounds__(256) conv_embed(const float* __restrict__ embed) {
    int i = blockIdx.x * blockDim.x + threadIdx.x;
    if (i < 10000 * HD / 4) {
        float4 v = ((const float4*)embed)[i];
        __half2 a = __floats2half2_rn(v.x, v.y);
        __half2 b = __floats2half2_rn(v.z, v.w);
        uint2 o;
        o.x = *(unsigned*)&a;
        o.y = *(unsigned*)&b;
        ((uint2*)g_embed_h)[i] = o;
    }
}

// ---------------- Wih0 fp16 fragment packing ---------------------------------
__global__ void __launch_bounds__(256) pack_w0(const float* __restrict__ Wih0) {
    int idx = blockIdx.x * blockDim.x + threadIdx.x;
    if (idx < (NG / 8) * 32 * 32) {
        int lane = idx & 31;
        int kt   = (idx >> 5) & 31;
        int n8   = idx >> 10;
        int n = n8 * 8 + (lane >> 2);
        int k = kt * 16 + 2 * (lane & 3);
        const float* p = Wih0 + (size_t)n * HD + k;
        __half2 lo = __floats2half2_rn(p[0], p[1]);
        __half2 hi = __floats2half2_rn(p[8], p[9]);
        uint2 v;
        v.x = *(unsigned*)&lo;
        v.y = *(unsigned*)&hi;
        g_W0f[idx] = v;
    }
}

// ---------------- recurrent weight packing -----------------------------------
__global__ void __launch_bounds__(256) prep_weights(
    const float* __restrict__ Whh0, const float* __restrict__ Wih1,
    const float* __restrict__ Whh1)
{
    int bk = blockIdx.x;
    int u0 = bk * UPB;
    for (int idx = threadIdx.x; idx < 4 * NKT * 32; idx += 256) {
        int lane = idx & 31;
        int kt   = (idx >> 5) % NKT;
        int gt   = (idx >> 5) / NKT;
        const float* W; int kbase;
        if (kt < 64)       { W = Whh0; kbase = kt * 16; }
        else if (kt < 128) { W = Wih1; kbase = (kt - 64) * 16; }
        else               { W = Whh1; kbase = (kt - 128) * 16; }
        int row = gt * HU + u0 + (lane >> 2);
        const float* p = W + (size_t)row * HU + kbase + 2 * (lane & 3);
        __half2 lo = __floats2half2_rn(p[0], p[1]);
        __half2 hi = __floats2half2_rn(p[8], p[9]);
        uint2 v;
        v.x = *(unsigned*)&lo;
        v.y = *(unsigned*)&hi;
        g_Wf[(((size_t)bk * 4 + gt) * NKT + kt) * 32 + lane] = v;
    }
}

// ---------------- precompute: Gpre = embed[y] @ Wih0^T + bih0 + bhh0 ---------
__global__ void __launch_bounds__(256) precompute_kernel(
    const int* __restrict__ y, const float* __restrict__ bih0,
    const float* __restrict__ bhh0)
{
    __shared__ __half Asm[128 * 72];
    __shared__ uint2  Bsm[16 * 4 * 32];
    __shared__ int ysm[128];

    int tid  = threadIdx.x;
    int lane = tid & 31;
    int w    = tid >> 5;
    int wm   = w & 3;
    int wn   = w >> 2;
    int n0   = blockIdx.x * 128;
    int m0   = blockIdx.y * 128;

    if (tid < 128) ysm[tid] = y[(tid & 63) * TT + blockIdx.y * 2 + (tid >> 6)];
    __syncthreads();

    unsigned asm_base = (unsigned)__cvta_generic_to_shared(Asm);
    unsigned bsm_base = (unsigned)__cvta_generic_to_shared(Bsm);

    float acc[2][8][4];
#pragma unroll
    for (int i = 0; i < 2; i++)
#pragma unroll
        for (int j = 0; j < 8; j++)
#pragma unroll
            for (int k = 0; k < 4; k++) acc[i][j][k] = 0.f;

    for (int kc = 0; kc < 8; kc++) {
#pragma unroll
        for (int j = 0; j < 4; j++) {
            int e = tid + j * 256;
            int r = e >> 3, sg = e & 7;
            const __half* g = g_embed_h + (size_t)ysm[r] * HD + kc * 64 + sg * 8;
            unsigned dst = asm_base + (unsigned)(r * 72 + sg * 8) * 2u;
            asm volatile("cp.async.cg.shared.global [%0], [%1], 16;" :: "r"(dst), "l"(g));
        }
#pragma unroll
        for (int j = 0; j < 4; j++) {
            int e = tid + j * 256;
            int n8l = e >> 6, w16 = e & 63;
            const uint2* src = g_W0f +
                ((size_t)(n0 / 8 + n8l) * 32 + kc * 4) * 32 + w16 * 2;
            unsigned dst = bsm_base + (unsigned)e * 16u;
            asm volatile("cp.async.cg.shared.global [%0], [%1], 16;" :: "r"(dst), "l"(src));
        }
        asm volatile("cp.async.commit_group;");
        asm volatile("cp.async.wait_group 0;");
        __syncthreads();

#pragma unroll
        for (int kt = 0; kt < 4; kt++) {
            unsigned a0[4], a1[4];
            ldmA72(a0, Asm, wm * 32,      kt * 16, lane);
            ldmA72(a1, Asm, wm * 32 + 16, kt * 16, lane);
#pragma unroll
            for (int nj = 0; nj < 8; nj++) {
                uint2 bb = Bsm[((wn * 8 + nj) * 4 + kt) * 32 + lane];
                mma16h(acc[0][nj], a0, (const unsigned*)&bb);
                mma16h(acc[1][nj], a1, (const unsigned*)&bb);
            }
        }
        __syncthreads();
    }

#pragma unroll
    for (int mt = 0; mt < 2; mt++) {
#pragma unroll
        for (int nj = 0; nj < 8; nj++) {
            float* c = acc[mt][nj];
            int row = wm * 32 + mt * 16 + (lane >> 2);
            int col = n0 + wn * 64 + nj * 8 + 2 * (lane & 3);
            float bb0 = bih0[col] + bhh0[col];
            float bb1 = bih0[col + 1] + bhh0[col + 1];
            *(float2*)(g_Gpre + (size_t)(m0 + row) * NG + col) =
                make_float2(c[0] + bb0, c[1] + bb1);
            *(float2*)(g_Gpre + (size_t)(m0 + row + 8) * NG + col) =
                make_float2(c[2] + bb0, c[3] + bb1);
        }
    }
}

// ---------------- persistent LSTM kernel (512 threads, dual-chunk) -----------
__global__ void __launch_bounds__(THREADS, 1) lstm_persistent(
    const float* __restrict__ bih1, const float* __restrict__ bhh1,
    float* __restrict__ out)
{
    extern __shared__ char smem[];
    uint2* Wsm  = (uint2*)smem;
    char*  AbC  = smem + ABUF_OFF;
    float* gsm  = (float*)(smem + ABUF_OFF);     // alias; used only post-GEMM
    float* bsum = (float*)(smem + BSUM_OFF);

    const int tid  = threadIdx.x;
    const int lane = tid & 31;
    const int w    = tid >> 5;
    const int mh   = w & 1;            // batch half
    const int kq   = (w >> 1) & 3;     // k16 quarter within 64-wide chunk
    const int cp   = w >> 3;           // chunk parity within a pair
    const int bk   = blockIdx.x;
    const int u0   = bk * UPB;

    const unsigned ab_base = (unsigned)__cvta_generic_to_shared(AbC);

    // resident weights
    {
        const uint4* src = (const uint4*)(g_Wf + (size_t)bk * 4 * NKT * 32);
        uint4* dst = (uint4*)Wsm;
        for (int i = tid; i < 4 * NKT * 32 / 2; i += THREADS) dst[i] = src[i];
    }
    if (tid < 32) {
        int g = tid >> 3, uu2 = tid & 7;
        bsum[tid] = bih1[g * HU + u0 + uu2] + bhh1[g * HU + u0 + uu2];
    }
    __syncthreads();

    const int eb = tid >> 3;           // batch index for epilogue (0..63)
    const int uu = tid & 7;
    const int u  = u0 + uu;

    float cr[2] = {0.f, 0.f};          // c-state per layer for this (b,u)
    float acc[2][4][4];

    const __half* h0r; __half* h0w; const __half* h1r; __half* h1w;

    // issue a pair of 64-wide chunks (c, c+1); one cp.async 16B per thread per chunk
    auto issue_pair = [&](int layer, int c) {
#pragma unroll
        for (int j = 0; j < 2; j++) {
            int cc = c + j;
            const __half* src; int koff;
            if (layer == 0)   { src = h0r; koff = cc * 64; }
            else if (cc < 16) { src = h0w; koff = cc * 64; }
            else              { src = h1r; koff = (cc - 16) * 64; }
            unsigned sbase = ab_base + (unsigned)(cc & 3) * STAGE_BYTES;
            int r = tid >> 3, sg = tid & 7;
            const __half* g = src + (size_t)r * HU + koff + sg * 8;
            unsigned dst = sbase + (unsigned)r * 128u +
                           (((unsigned)sg << 4) ^ (((unsigned)r & 7u) << 4));
            asm volatile("cp.async.cg.shared.global [%0], [%1], 16;" :: "r"(dst), "l"(g));
        }
        asm volatile("cp.async.commit_group;");
    };

    // RACE-FIX (R7): wait + barrier BEFORE issuing the next pair. The barrier
    // orders every warp's ldmatrix reads of stages (c+2)&3,(c+3)&3 (done in
    // iteration c-2) before the cp.async overwrite. Only one group is ever in
    // flight at the wait, so wait_group 0 is exact.
    auto gemm_range = [&](int layer, int cb, int ce) {
        const int ktbase = layer ? 64 : 0;
        issue_pair(layer, cb);
        for (int c = cb; c < ce; c += 2) {
            asm volatile("cp.async.wait_group 0;");
            __syncthreads();
            if (c + 2 < ce) issue_pair(layer, c + 2);
            const int cc = c + cp;
            unsigned cur = ab_base + (unsigned)(cc & 3) * STAGE_BYTES;
            const int kti = ktbase + cc * 4 + kq;
            unsigned a0[4], a1[4];
            ldmA_sw(a0, cur, mh * 32,      kq * 16, lane);
            ldmA_sw(a1, cur, mh * 32 + 16, kq * 16, lane);
#pragma unroll
            for (int gt = 0; gt < 4; gt++) {
                uint2 bb = Wsm[(gt * NKT + kti) * 32 + lane];
                mma16h(acc[0][gt], a0, (const unsigned*)&bb);
                mma16h(acc[1][gt], a1, (const unsigned*)&bb);
            }
        }
    };

    // fold 16 warp-accumulators into 16 gsm slots (2 passes), slots aliased on stages
    auto fold = [&]() {
        __syncthreads();   // all ldmatrix reads done before gsm writes
        const int s4  = (kq & 1) * 2 + cp;
        const int row = mh * 32 + (lane >> 2);
        const int cb2 = 2 * (lane & 3);
        if (kq < 2) {
#pragma unroll
            for (int mt = 0; mt < 2; mt++)
#pragma unroll
                for (int gt = 0; gt < 4; gt++) {
                    float* base = &gsm[(s4 * 4 + gt) * 512 + (row + mt * 16) * 8 + cb2];
                    *(float2*)base        = make_float2(acc[mt][gt][0], acc[mt][gt][1]);
                    *(float2*)(base + 64) = make_float2(acc[mt][gt][2], acc[mt][gt][3]);
                }
        }
        __syncthreads();
        if (kq >= 2) {
#pragma unroll
            for (int mt = 0; mt < 2; mt++)
#pragma unroll
                for (int gt = 0; gt < 4; gt++) {
                    float* base = &gsm[(s4 * 4 + gt) * 512 + (row + mt * 16) * 8 + cb2];
                    float2 v0 = *(float2*)base;
                    float2 v1 = *(float2*)(base + 64);
                    v0.x += acc[mt][gt][0]; v0.y += acc[mt][gt][1];
                    v1.x += acc[mt][gt][2]; v1.y += acc[mt][gt][3];
                    *(float2*)base        = v0;
                    *(float2*)(base + 64) = v1;
                }
        }
        __syncthreads();
    };

    auto gate = [&](int g) {
        return gsm[(0 * 4 + g) * 512 + eb * 8 + uu] +
               gsm[(1 * 4 + g) * 512 + eb * 8 + uu] +
               gsm[(2 * 4 + g) * 512 + eb * 8 + uu] +
               gsm[(3 * 4 + g) * 512 + eb * 8 + uu];
    };

    auto waitf = [&](unsigned* flag, unsigned v) {
        if (tid == 0) {
            unsigned f;
            do {
                asm volatile("ld.global.acquire.gpu.u32 %0, [%1];"
                             : "=r"(f) : "l"(flag) : "memory");
            } while (f < v);
        }
        __syncthreads();
    };
    auto arrive = [&](unsigned* cnt, unsigned* flag, unsigned v) {
        __syncthreads();
        if (tid == 0) {
            __threadfence();
            if (atomicAdd(cnt, 1u) == v * NBLK - 1u)
                asm volatile("st.global.release.gpu.u32 [%0], %1;"
                             :: "l"(flag), "r"(v) : "memory");
        }
    };

    for (int t = 0; t < TT; ++t) {
        const int pp = t & 1;
        h0r = g_h0[pp]; h0w = g_h0[pp ^ 1];
        h1r = g_h1[pp]; h1w = g_h1[pp ^ 1];

        // prefetch Gpre operands for this step's layer-0 epilogue
        float pre[4];
        {
            const float* gp = g_Gpre + ((size_t)t * BQ + eb) * NG;
#pragma unroll
            for (int g = 0; g < 4; g++) pre[g] = gp[g * HU + u];
        }

        // ================= layer 0 =================
#pragma unroll
        for (int i = 0; i < 2; i++)
#pragma unroll
            for (int j = 0; j < 4; j++)
#pragma unroll
                for (int k = 0; k < 4; k++) acc[i][j][k] = 0.f;
        gemm_range(0, 0, 16);
        fold();
        {
            float gi = gate(0) + pre[0];
            float gf = gate(1) + pre[1];
            float gg = gate(2) + pre[2];
            float go = gate(3) + pre[3];
            float cv = fsig(gf) * cr[0] + fsig(gi) * ftanh(gg);
            cr[0] = cv;
            h0w[eb * HU + u] = __float2half_rn(fsig(go) * ftanh(cv));
        }
        arrive(&g_cntA, &g_flagA, (unsigned)t + 1u);   // includes __syncthreads

        // ================= layer 1 =================
#pragma unroll
        for (int i = 0; i < 2; i++)
#pragma unroll
            for (int j = 0; j < 4; j++)
#pragma unroll
                for (int k = 0; k < 4; k++) acc[i][j][k] = 0.f;

        if (t > 0) waitf(&g_flagB, (unsigned)t);       // h1r final
        gemm_range(1, 16, 32);                          // h1r half (overlaps barrier A)
        waitf(&g_flagA, (unsigned)t + 1u);              // h0w ready from all blocks
        gemm_range(1, 0, 16);                           // h0w half
        fold();
        {
            float gi = gate(0) + bsum[uu];
            float gf = gate(1) + bsum[8 + uu];
            float gg = gate(2) + bsum[16 + uu];
            float go = gate(3) + bsum[24 + uu];
            float cv = fsig(gf) * cr[1] + fsig(gi) * ftanh(gg);
            cr[1] = cv;
            float hv = fsig(go) * ftanh(cv);
            h1w[eb * HU + u] = __float2half_rn(hv);
            out[((size_t)eb * TT + t) * HU + u] = hv;
        }
        if (t + 1 < TT) arrive(&g_cntB, &g_flagB, (unsigned)t + 1u);
        else            __syncthreads();
    }
}

// ---------------------------------------------------------------------------
extern "C" void kernel_launch(void* const* d_in, const int* in_sizes, int n_in,
                              void* d_out, int out_size) {
    const int*   y     = (const int*)  d_in[0];
    const float* embed = (const float*)d_in[1];
    const float* Wih0  = (const float*)d_in[2];
    const float* Whh0  = (const float*)d_in[3];
    const float* bih0  = (const float*)d_in[4];
    const float* bhh0  = (const float*)d_in[5];
    const float* Wih1  = (const float*)d_in[6];
    const float* Whh1  = (const float*)d_in[7];
    const float* bih1  = (const float*)d_in[8];
    const float* bhh1  = (const float*)d_in[9];
    float* out = (float*)d_out;

    cudaFuncSetAttribute(lstm_persistent,
                         cudaFuncAttributeMaxDynamicSharedMemorySize, SMEM_TOTAL);

    zero_kernel<<<(BQ * HU / 2 + 255) / 256, 256>>>();
    conv_embed<<<(10000 * HD / 4 + 255) / 256, 256>>>(embed);
    pack_w0<<<((NG / 8) * 32 * 32 + 255) / 256, 256>>>(Wih0);
    prep_weights<<<NBLK, 256>>>(Whh0, Wih1, Whh1);
    precompute_kernel<<<dim3(NG / 128, TT / 2), 256>>>(y, bih0, bhh0);
    lstm_persistent<<<NBLK, THREADS, SMEM_TOTAL>>>(bih1, bhh1, out);

    (void)in_sizes; (void)n_in; (void)out_size;
}

// round 8
// speedup vs baseline: 1.0099x; 1.0099x over previous
#include <cuda_runtime.h>
#include <cuda_fp16.h>

#define BQ 64
#define TT 256
#define HU 1024
#define HD 512
#define NG 4096
#define NBLK 128
#define UPB 8           // hidden units per block
#define NKT 192         // k16 tiles: 64 (Whh0) + 64 (Wih1) + 64 (Whh1)
#define THREADS 512

// ---------------- static device scratch (no allocation allowed) -------------
__device__ float  g_Gpre[(size_t)TT * BQ * NG];
__device__ __half g_h0[2][BQ * HU];
__device__ __half g_h1[2][BQ * HU];
__device__ uint2  g_Wf[(size_t)NBLK * 4 * NKT * 32];   // recurrent weights, frag order
__device__ __half g_embed_h[(size_t)10000 * HD];       // fp16 embed
__device__ uint2  g_W0f[(size_t)(NG / 8) * 32 * 32];   // Wih0 fp16, frag order
__device__ unsigned g_cntA, g_cntB, g_flagA, g_flagB;

// smem layout for persistent kernel
#define WSM_BYTES   (4 * NKT * 32 * 8)                 // 196608
#define ABUF_OFF    WSM_BYTES
#define STAGE_BYTES 8192                               // 64 rows x 128B, SW128 swizzle
#define BSUM_OFF    (ABUF_OFF + 4 * STAGE_BYTES)       // 229376
#define SMEM_TOTAL  (BSUM_OFF + 128)                   // 229504

// ---------------- helpers ----------------------------------------------------
__device__ __forceinline__ void mma16h(float* c, const unsigned* a, const unsigned* b) {
    asm volatile(
        "mma.sync.aligned.m16n8k16.row.col.f32.f16.f16.f32 "
        "{%0,%1,%2,%3}, {%4,%5,%6,%7}, {%8,%9}, {%0,%1,%2,%3};\n"
        : "+f"(c[0]), "+f"(c[1]), "+f"(c[2]), "+f"(c[3])
        : "r"(a[0]), "r"(a[1]), "r"(a[2]), "r"(a[3]), "r"(b[0]), "r"(b[1]));
}
__device__ __forceinline__ void ldmA72(unsigned* a, const __half* buf, int mrow,
                                       int kcol, int lane) {
    int row = mrow + (lane & 7) + ((lane >> 3) & 1) * 8;
    int col = kcol + (lane >> 4) * 8;
    unsigned addr = (unsigned)__cvta_generic_to_shared(buf + row * 72 + col);
    asm volatile("ldmatrix.sync.aligned.m8n8.x4.shared.b16 {%0,%1,%2,%3}, [%4];"
                 : "=r"(a[0]), "=r"(a[1]), "=r"(a[2]), "=r"(a[3]) : "r"(addr));
}
// A-frag load from SW128-swizzled pitch-64-halves tile (persistent kernel)
__device__ __forceinline__ void ldmA_sw(unsigned* a, unsigned base, int mrow,
                                        int kcol, int lane) {
    int row = mrow + (lane & 7) + ((lane >> 3) & 1) * 8;
    unsigned sl = (unsigned)(kcol >> 3) + (unsigned)(lane >> 4);
    unsigned off = (unsigned)row * 128u + ((sl << 4) ^ (((unsigned)row & 7u) << 4));
    unsigned addr = base + off;
    asm volatile("ldmatrix.sync.aligned.m8n8.x4.shared.b16 {%0,%1,%2,%3}, [%4];"
                 : "=r"(a[0]), "=r"(a[1]), "=r"(a[2]), "=r"(a[3]) : "r"(addr));
}
__device__ __forceinline__ float fsig(float x) {
    return __fdividef(1.f, 1.f + __expf(-x));
}
__device__ __forceinline__ float ftanh(float x) {
    return __fdividef(2.f, 1.f + __expf(-2.f * x)) - 1.f;
}

// ---------------- init -------------------------------------------------------
__global__ void zero_kernel() {
    int i = blockIdx.x * blockDim.x + threadIdx.x;
    int n = BQ * HU / 2;
    if (i < n) {
        ((unsigned*)g_h0[0])[i] = 0u;
        ((unsigned*)g_h1[0])[i] = 0u;
    }
    if (i == 0) { g_cntA = 0u; g_cntB = 0u; g_flagA = 0u; g_flagB = 0u; }
}

// ---------------- fp32 -> fp16 embed conversion ------------------------------
__global__ void __launch_bounds__(256) conv_embed(const float* __restrict__ embed) {
    int i = blockIdx.x * blockDim.x + threadIdx.x;
    if (i < 10000 * HD / 4) {
        float4 v = ((const float4*)embed)[i];
        __half2 a = __floats2half2_rn(v.x, v.y);
        __half2 b = __floats2half2_rn(v.z, v.w);
        uint2 o;
        o.x = *(unsigned*)&a;
        o.y = *(unsigned*)&b;
        ((uint2*)g_embed_h)[i] = o;
    }
}

// ---------------- Wih0 fp16 fragment packing ---------------------------------
__global__ void __launch_bounds__(256) pack_w0(const float* __restrict__ Wih0) {
    int idx = blockIdx.x * blockDim.x + threadIdx.x;
    if (idx < (NG / 8) * 32 * 32) {
        int lane = idx & 31;
        int kt   = (idx >> 5) & 31;
        int n8   = idx >> 10;
        int n = n8 * 8 + (lane >> 2);
        int k = kt * 16 + 2 * (lane & 3);
        const float* p = Wih0 + (size_t)n * HD + k;
        __half2 lo = __floats2half2_rn(p[0], p[1]);
        __half2 hi = __floats2half2_rn(p[8], p[9]);
        uint2 v;
        v.x = *(unsigned*)&lo;
        v.y = *(unsigned*)&hi;
        g_W0f[idx] = v;
    }
}

// ---------------- recurrent weight packing -----------------------------------
__global__ void __launch_bounds__(256) prep_weights(
    const float* __restrict__ Whh0, const float* __restrict__ Wih1,
    const float* __restrict__ Whh1)
{
    int bk = blockIdx.x;
    int u0 = bk * UPB;
    for (int idx = threadIdx.x; idx < 4 * NKT * 32; idx += 256) {
        int lane = idx & 31;
        int kt   = (idx >> 5) % NKT;
        int gt   = (idx >> 5) / NKT;
        const float* W; int kbase;
        if (kt < 64)       { W = Whh0; kbase = kt * 16; }
        else if (kt < 128) { W = Wih1; kbase = (kt - 64) * 16; }
        else               { W = Whh1; kbase = (kt - 128) * 16; }
        int row = gt * HU + u0 + (lane >> 2);
        const float* p = W + (size_t)row * HU + kbase + 2 * (lane & 3);
        __half2 lo = __floats2half2_rn(p[0], p[1]);
        __half2 hi = __floats2half2_rn(p[8], p[9]);
        uint2 v;
        v.x = *(unsigned*)&lo;
        v.y = *(unsigned*)&hi;
        g_Wf[(((size_t)bk * 4 + gt) * NKT + kt) * 32 + lane] = v;
    }
}

// ---------------- precompute: Gpre = embed[y] @ Wih0^T + bih0 + bhh0 ---------
__global__ void __launch_bounds__(256) precompute_kernel(
    const int* __restrict__ y, const float* __restrict__ bih0,
    const float* __restrict__ bhh0)
{
    __shared__ __half Asm[128 * 72];
    __shared__ uint2  Bsm[16 * 4 * 32];
    __shared__ int ysm[128];

    int tid  = threadIdx.x;
    int lane = tid & 31;
    int w    = tid >> 5;
    int wm   = w & 3;
    int wn   = w >> 2;
    int n0   = blockIdx.x * 128;
    int m0   = blockIdx.y * 128;

    if (tid < 128) ysm[tid] = y[(tid & 63) * TT + blockIdx.y * 2 + (tid >> 6)];
    __syncthreads();

    unsigned asm_base = (unsigned)__cvta_generic_to_shared(Asm);
    unsigned bsm_base = (unsigned)__cvta_generic_to_shared(Bsm);

    float acc[2][8][4];
#pragma unroll
    for (int i = 0; i < 2; i++)
#pragma unroll
        for (int j = 0; j < 8; j++)
#pragma unroll
            for (int k = 0; k < 4; k++) acc[i][j][k] = 0.f;

    for (int kc = 0; kc < 8; kc++) {
#pragma unroll
        for (int j = 0; j < 4; j++) {
            int e = tid + j * 256;
            int r = e >> 3, sg = e & 7;
            const __half* g = g_embed_h + (size_t)ysm[r] * HD + kc * 64 + sg * 8;
            unsigned dst = asm_base + (unsigned)(r * 72 + sg * 8) * 2u;
            asm volatile("cp.async.cg.shared.global [%0], [%1], 16;" :: "r"(dst), "l"(g));
        }
#pragma unroll
        for (int j = 0; j < 4; j++) {
            int e = tid + j * 256;
            int n8l = e >> 6, w16 = e & 63;
            const uint2* src = g_W0f +
                ((size_t)(n0 / 8 + n8l) * 32 + kc * 4) * 32 + w16 * 2;
            unsigned dst = bsm_base + (unsigned)e * 16u;
            asm volatile("cp.async.cg.shared.global [%0], [%1], 16;" :: "r"(dst), "l"(src));
        }
        asm volatile("cp.async.commit_group;");
        asm volatile("cp.async.wait_group 0;");
        __syncthreads();

#pragma unroll
        for (int kt = 0; kt < 4; kt++) {
            unsigned a0[4], a1[4];
            ldmA72(a0, Asm, wm * 32,      kt * 16, lane);
            ldmA72(a1, Asm, wm * 32 + 16, kt * 16, lane);
#pragma unroll
            for (int nj = 0; nj < 8; nj++) {
                uint2 bb = Bsm[((wn * 8 + nj) * 4 + kt) * 32 + lane];
                mma16h(acc[0][nj], a0, (const unsigned*)&bb);
                mma16h(acc[1][nj], a1, (const unsigned*)&bb);
            }
        }
        __syncthreads();
    }

#pragma unroll
    for (int mt = 0; mt < 2; mt++) {
#pragma unroll
        for (int nj = 0; nj < 8; nj++) {
            float* c = acc[mt][nj];
            int row = wm * 32 + mt * 16 + (lane >> 2);
            int col = n0 + wn * 64 + nj * 8 + 2 * (lane & 3);
            float bb0 = bih0[col] + bhh0[col];
            float bb1 = bih0[col + 1] + bhh0[col + 1];
            *(float2*)(g_Gpre + (size_t)(m0 + row) * NG + col) =
                make_float2(c[0] + bb0, c[1] + bb1);
            *(float2*)(g_Gpre + (size_t)(m0 + row + 8) * NG + col) =
                make_float2(c[2] + bb0, c[3] + bb1);
        }
    }
}

// ---------------- persistent LSTM kernel (512 threads, LDG->STS staging) -----
__global__ void __launch_bounds__(THREADS, 1) lstm_persistent(
    const float* __restrict__ bih1, const float* __restrict__ bhh1,
    float* __restrict__ out)
{
    extern __shared__ char smem[];
    uint2* Wsm  = (uint2*)smem;
    float* gsm  = (float*)(smem + ABUF_OFF);     // alias stage region; post-GEMM only
    float* bsum = (float*)(smem + BSUM_OFF);

    const int tid  = threadIdx.x;
    const int lane = tid & 31;
    const int w    = tid >> 5;
    const int mh   = w & 1;            // batch half
    const int kq   = (w >> 1) & 3;     // k16 quarter within 64-wide chunk
    const int cp   = w >> 3;           // chunk parity within a pair
    const int bk   = blockIdx.x;
    const int u0   = bk * UPB;

    const unsigned ab_base = (unsigned)__cvta_generic_to_shared(smem + ABUF_OFF);

    // per-thread staging address components (16B per chunk per thread)
    const int sr = tid >> 3, sg = tid & 7;
    const unsigned sts_off = (unsigned)sr * 128u +
                             (((unsigned)sg << 4) ^ (((unsigned)sr & 7u) << 4));
    const unsigned ldg_off = (unsigned)sr * HU + sg * 8;   // element offset into h

    // resident weights
    {
        const uint4* src = (const uint4*)(g_Wf + (size_t)bk * 4 * NKT * 32);
        uint4* dst = (uint4*)Wsm;
        for (int i = tid; i < 4 * NKT * 32 / 2; i += THREADS) dst[i] = src[i];
    }
    if (tid < 32) {
        int g = tid >> 3, uu2 = tid & 7;
        bsum[tid] = bih1[g * HU + u0 + uu2] + bhh1[g * HU + u0 + uu2];
    }
    __syncthreads();

    const int eb = tid >> 3;           // batch index for epilogue (0..63)
    const int uu = tid & 7;
    const int u  = u0 + uu;

    float cr[2] = {0.f, 0.f};          // c-state per layer for this (b,u)
    float acc[2][4][4];

    const __half* h0r; __half* h0w; const __half* h1r; __half* h1w;

    // LDG a pair of chunks (c, c+1) into registers (L2-coherent, L1-bypass)
    auto ldg_pair = [&](int layer, int c, uint4* buf) {
#pragma unroll
        for (int j = 0; j < 2; j++) {
            int cc = c + j;
            const __half* src; int koff;
            if (layer == 0)   { src = h0r; koff = cc * 64; }
            else if (cc < 16) { src = h0w; koff = cc * 64; }
            else              { src = h1r; koff = (cc - 16) * 64; }
            const __half* g = src + ldg_off + koff;
            asm volatile("ld.global.cg.v4.b32 {%0,%1,%2,%3}, [%4];"
                         : "=r"(buf[j].x), "=r"(buf[j].y),
                           "=r"(buf[j].z), "=r"(buf[j].w) : "l"(g));
        }
    };
    // STS a buffered pair into its SW128-swizzled stages
    auto sts_pair = [&](int c, const uint4* buf) {
#pragma unroll
        for (int j = 0; j < 2; j++) {
            unsigned dst = ab_base + (unsigned)((c + j) & 3) * STAGE_BYTES + sts_off;
            asm volatile("st.shared.v4.b32 [%0], {%1,%2,%3,%4};"
                         :: "r"(dst), "r"(buf[j].x), "r"(buf[j].y),
                            "r"(buf[j].z), "r"(buf[j].w));
        }
    };

    // R8 pipeline: LDG(c+4) issued at iter c, STS'd at iter c+2, computed at
    // iter c+4 -> 2 full iterations of global-latency cover with only 4 stages.
    // The top-of-iteration __syncthreads orders (a) STS(pair c) [iter c-2]
    // before compute(pair c), and (b) compute(pair c-2)'s ldmatrix reads of
    // stages (c+2)&3,(c+3)&3 before this iteration's STS overwrites them.
    auto gemm_range = [&](int layer, int cb, int ce) {
        const int ktbase = layer ? 64 : 0;
        uint4 buf[2];
        ldg_pair(layer, cb, buf);
        sts_pair(cb, buf);                       // prologue (stalls on first LDG)
        if (cb + 2 < ce) ldg_pair(layer, cb + 2, buf);
        for (int c = cb; c < ce; c += 2) {
            __syncthreads();
            if (c + 2 < ce) {
                sts_pair(c + 2, buf);
                if (c + 4 < ce) ldg_pair(layer, c + 4, buf);
            }
            const int cc = c + cp;
            unsigned cur = ab_base + (unsigned)(cc & 3) * STAGE_BYTES;
            const int kti = ktbase + cc * 4 + kq;
            unsigned a0[4], a1[4];
            ldmA_sw(a0, cur, mh * 32,      kq * 16, lane);
            ldmA_sw(a1, cur, mh * 32 + 16, kq * 16, lane);
#pragma unroll
            for (int gt = 0; gt < 4; gt++) {
                uint2 bb = Wsm[(gt * NKT + kti) * 32 + lane];
                mma16h(acc[0][gt], a0, (const unsigned*)&bb);
                mma16h(acc[1][gt], a1, (const unsigned*)&bb);
            }
        }
    };

    // fold 16 warp-accumulators into 16 gsm slots (2 passes), aliased on stages
    auto fold = [&]() {
        __syncthreads();   // all ldmatrix reads done before gsm writes
        const int s4  = (kq & 1) * 2 + cp;
        const int row = mh * 32 + (lane >> 2);
        const int cb2 = 2 * (lane & 3);
        if (kq < 2) {
#pragma unroll
            for (int mt = 0; mt < 2; mt++)
#pragma unroll
                for (int gt = 0; gt < 4; gt++) {
                    float* base = &gsm[(s4 * 4 + gt) * 512 + (row + mt * 16) * 8 + cb2];
                    *(float2*)base        = make_float2(acc[mt][gt][0], acc[mt][gt][1]);
                    *(float2*)(base + 64) = make_float2(acc[mt][gt][2], acc[mt][gt][3]);
                }
        }
        __syncthreads();
        if (kq >= 2) {
#pragma unroll
            for (int mt = 0; mt < 2; mt++)
#pragma unroll
                for (int gt = 0; gt < 4; gt++) {
                    float* base = &gsm[(s4 * 4 + gt) * 512 + (row + mt * 16) * 8 + cb2];
                    float2 v0 = *(float2*)base;
                    float2 v1 = *(float2*)(base + 64);
                    v0.x += acc[mt][gt][0]; v0.y += acc[mt][gt][1];
                    v1.x += acc[mt][gt][2]; v1.y += acc[mt][gt][3];
                    *(float2*)base        = v0;
                    *(float2*)(base + 64) = v1;
                }
        }
        __syncthreads();
    };

    auto gate = [&](int g) {
        return gsm[(0 * 4 + g) * 512 + eb * 8 + uu] +
               gsm[(1 * 4 + g) * 512 + eb * 8 + uu] +
               gsm[(2 * 4 + g) * 512 + eb * 8 + uu] +
               gsm[(3 * 4 + g) * 512 + eb * 8 + uu];
    };

    auto waitf = [&](unsigned* flag, unsigned v) {
        if (tid == 0) {
            unsigned f;
            do {
                asm volatile("ld.global.acquire.gpu.u32 %0, [%1];"
                             : "=r"(f) : "l"(flag) : "memory");
            } while (f < v);
        }
        __syncthreads();
    };
    auto arrive = [&](unsigned* cnt, unsigned* flag, unsigned v) {
        __syncthreads();
        if (tid == 0) {
            __threadfence();
            if (atomicAdd(cnt, 1u) == v * NBLK - 1u)
                asm volatile("st.global.release.gpu.u32 [%0], %1;"
                             :: "l"(flag), "r"(v) : "memory");
        }
    };

    for (int t = 0; t < TT; ++t) {
        const int pp = t & 1;
        h0r = g_h0[pp]; h0w = g_h0[pp ^ 1];
        h1r = g_h1[pp]; h1w = g_h1[pp ^ 1];

        // prefetch Gpre operands for this step's layer-0 epilogue
        float pre[4];
        {
            const float* gp = g_Gpre + ((size_t)t * BQ + eb) * NG;
#pragma unroll
            for (int g = 0; g < 4; g++) pre[g] = gp[g * HU + u];
        }

        // ================= layer 0 =================
#pragma unroll
        for (int i = 0; i < 2; i++)
#pragma unroll
            for (int j = 0; j < 4; j++)
#pragma unroll
                for (int k = 0; k < 4; k++) acc[i][j][k] = 0.f;
        gemm_range(0, 0, 16);
        fold();
        {
            float gi = gate(0) + pre[0];
            float gf = gate(1) + pre[1];
            float gg = gate(2) + pre[2];
            float go = gate(3) + pre[3];
            float cv = fsig(gf) * cr[0] + fsig(gi) * ftanh(gg);
            cr[0] = cv;
            h0w[eb * HU + u] = __float2half_rn(fsig(go) * ftanh(cv));
        }
        arrive(&g_cntA, &g_flagA, (unsigned)t + 1u);   // includes __syncthreads

        // ================= layer 1 =================
#pragma unroll
        for (int i = 0; i < 2; i++)
#pragma unroll
            for (int j = 0; j < 4; j++)
#pragma unroll
                for (int k = 0; k < 4; k++) acc[i][j][k] = 0.f;

        if (t > 0) waitf(&g_flagB, (unsigned)t);       // h1r final
        gemm_range(1, 16, 32);                          // h1r half (overlaps barrier A)
        waitf(&g_flagA, (unsigned)t + 1u);              // h0w ready from all blocks
        gemm_range(1, 0, 16);                           // h0w half
        fold();
        {
            float gi = gate(0) + bsum[uu];
            float gf = gate(1) + bsum[8 + uu];
            float gg = gate(2) + bsum[16 + uu];
            float go = gate(3) + bsum[24 + uu];
            float cv = fsig(gf) * cr[1] + fsig(gi) * ftanh(gg);
            cr[1] = cv;
            float hv = fsig(go) * ftanh(cv);
            h1w[eb * HU + u] = __float2half_rn(hv);
            out[((size_t)eb * TT + t) * HU + u] = hv;
        }
        if (t + 1 < TT) arrive(&g_cntB, &g_flagB, (unsigned)t + 1u);
        else            __syncthreads();
    }
}

// ---------------------------------------------------------------------------
extern "C" void kernel_launch(void* const* d_in, const int* in_sizes, int n_in,
                              void* d_out, int out_size) {
    const int*   y     = (const int*)  d_in[0];
    const float* embed = (const float*)d_in[1];
    const float* Wih0  = (const float*)d_in[2];
    const float* Whh0  = (const float*)d_in[3];
    const float* bih0  = (const float*)d_in[4];
    const float* bhh0  = (const float*)d_in[5];
    const float* Wih1  = (const float*)d_in[6];
    const float* Whh1  = (const float*)d_in[7];
    const float* bih1  = (const float*)d_in[8];
    const float* bhh1  = (const float*)d_in[9];
    float* out = (float*)d_out;

    cudaFuncSetAttribute(lstm_persistent,
                         cudaFuncAttributeMaxDynamicSharedMemorySize, SMEM_TOTAL);

    zero_kernel<<<(BQ * HU / 2 + 255) / 256, 256>>>();
    conv_embed<<<(10000 * HD / 4 + 255) / 256, 256>>>(embed);
    pack_w0<<<((NG / 8) * 32 * 32 + 255) / 256, 256>>>(Wih0);
    prep_weights<<<NBLK, 256>>>(Whh0, Wih1, Whh1);
    precompute_kernel<<<dim3(NG / 128, TT / 2), 256>>>(y, bih0, bhh0);
    lstm_persistent<<<NBLK, THREADS, SMEM_TOTAL>>>(bih1, bhh1, out);

    (void)in_sizes; (void)n_in; (void)out_size;
}